// round 1
// baseline (speedup 1.0000x reference)
#include <cuda_runtime.h>
#include <math.h>

#define B 64
#define NTOK 4096
#define D 64
#define S 8
#define HID 128
#define CHUNKS 8
#define NC (NTOK / CHUNKS)   /* 512 tokens per block */
#define TILE 128
#define TPB_MAIN 128

// ---------------- device scratch (no allocs allowed) ----------------
__device__ float g_slots[B * S * D];
__device__ float g_qhat[B * S * D];   // 0.125 * (q @ wk^T) * g_in
__device__ float g_sq[B * S];         // row sums of qhat
__device__ float g_cst[B * S];        // 0.125*(q~ . beta_in + q . bk)
__device__ float g_P[B * CHUNKS * S * D];  // partial P accumulators
__device__ float g_Td[B * CHUNKS * 16];    // per-chunk [T_i (8) | den_i (8)]
__device__ float g_wqk[D * D];        // wq @ wk^T
__device__ float g_bqk[D];            // bq @ wk^T
__device__ float g_wqbk[D];           // wq @ bk
__device__ float g_bqbk[1];           // bq . bk

// ---------------- precompute folded weight products ----------------
__global__ __launch_bounds__(256) void k_pre(const float* __restrict__ wq,
                                             const float* __restrict__ bq,
                                             const float* __restrict__ wk,
                                             const float* __restrict__ bk) {
    int t = threadIdx.x;
    for (int o = t; o < D * D; o += 256) {
        int e = o >> 6, e2 = o & 63;
        float s = 0.f;
        for (int d = 0; d < D; d++) s += wq[e * D + d] * wk[e2 * D + d];
        g_wqk[o] = s;
    }
    for (int e2 = t; e2 < D; e2 += 256) {
        float s = 0.f;
        for (int d = 0; d < D; d++) s += bq[d] * wk[e2 * D + d];
        g_bqk[e2] = s;
    }
    for (int e = t; e < D; e += 256) {
        float s = 0.f;
        for (int d = 0; d < D; d++) s += wq[e * D + d] * bk[d];
        g_wqbk[e] = s;
    }
    if (t == 0) {
        float s = 0.f;
        for (int d = 0; d < D; d++) s += bq[d] * bk[d];
        g_bqbk[0] = s;
    }
}

// ---------------- per-batch q-folding from current slots ----------------
// blockDim must be 256 (8 warps). s_sln: 512 floats, s_tmp: 1024 floats.
__device__ void compute_q_from_slots(int b, const float* s_slots,
                                     const float* __restrict__ g_sl,
                                     const float* __restrict__ be_sl,
                                     const float* __restrict__ g_in,
                                     const float* __restrict__ be_in,
                                     float* s_sln, float* s_tmp) {
    int tid = threadIdx.x;
    int w = tid >> 5, lane = tid & 31;
    // LayerNorm(slots) with g_sl/beta_sl: warp w handles slot w
    {
        float v0 = s_slots[w * 64 + lane];
        float v1 = s_slots[w * 64 + 32 + lane];
        float s = v0 + v1, s2 = v0 * v0 + v1 * v1;
#pragma unroll
        for (int off = 16; off; off >>= 1) {
            s += __shfl_xor_sync(0xffffffffu, s, off);
            s2 += __shfl_xor_sync(0xffffffffu, s2, off);
        }
        float m = s * (1.f / 64.f);
        float var = s2 * (1.f / 64.f) - m * m;
        float r = rsqrtf(var + 1e-5f);
        s_sln[w * 64 + lane] = (v0 - m) * r * g_sl[lane] + be_sl[lane];
        s_sln[w * 64 + 32 + lane] = (v1 - m) * r * g_sl[lane + 32] + be_sl[lane + 32];
    }
    __syncthreads();
    // q~ = sln @ wqk + bqk ; fold scale 0.125 and g_in/beta_in
    for (int rep = 0; rep < 2; rep++) {
        int idx = tid + rep * 256;
        int i = idx >> 6, e2 = idx & 63;
        float acc = g_bqk[e2];
#pragma unroll 8
        for (int e = 0; e < 64; e++) acc += s_sln[i * 64 + e] * g_wqk[e * 64 + e2];
        float qt = 0.125f * acc;
        float qh = qt * g_in[e2];
        g_qhat[b * S * D + idx] = qh;
        s_tmp[idx] = qh;
        s_tmp[512 + idx] = qt * be_in[e2];
    }
    __syncthreads();
    if (tid < S) {
        float sq = 0.f, cb = 0.f;
        for (int e2 = 0; e2 < 64; e2++) {
            sq += s_tmp[tid * 64 + e2];
            cb += s_tmp[512 + tid * 64 + e2];
        }
        float qb = g_bqbk[0];
        for (int e = 0; e < 64; e++) qb += s_sln[tid * 64 + e] * g_wqbk[e];
        g_sq[b * S + tid] = sq;
        g_cst[b * S + tid] = cb + 0.125f * qb;
    }
}

// ---------------- init: slots = mu + exp(ls)*noise, then q fold ----------------
__global__ __launch_bounds__(256) void k_init(const float* __restrict__ noise,
                                              const float* __restrict__ mu,
                                              const float* __restrict__ ls,
                                              const float* __restrict__ g_sl,
                                              const float* __restrict__ be_sl,
                                              const float* __restrict__ g_in,
                                              const float* __restrict__ be_in) {
    __shared__ float s_slots[512];
    __shared__ float s_sln[512];
    __shared__ float s_tmp[1024];
    int b = blockIdx.x, tid = threadIdx.x;
    for (int k = tid; k < 512; k += 256) {
        int d = k & 63;
        float v = mu[d] + expf(ls[d]) * noise[b * 512 + k];
        s_slots[k] = v;
        g_slots[b * 512 + k] = v;
    }
    __syncthreads();
    compute_q_from_slots(b, s_slots, g_sl, be_sl, g_in, be_in, s_sln, s_tmp);
}

// ---------------- main streaming pass (per iteration) ----------------
__global__ __launch_bounds__(TPB_MAIN) void k_main(const float* __restrict__ x) {
    __shared__ __align__(16) float xs[TILE * 65];
    __shared__ __align__(16) float attn_s[S * TILE];
    __shared__ __align__(16) float qh[S * D];
    __shared__ float sqs[S], csts[S];
    __shared__ float s_red[4][16];

    int b = blockIdx.y, c = blockIdx.x, tid = threadIdx.x;
    for (int k = tid; k < S * D; k += TPB_MAIN) qh[k] = g_qhat[b * S * D + k];
    if (tid < S) {
        sqs[tid] = g_sq[b * S + tid];
        csts[tid] = g_cst[b * S + tid];
    }

    float acc0 = 0.f, acc1 = 0.f, acc2 = 0.f, acc3 = 0.f;
    float Tl[S], dl[S];
#pragma unroll
    for (int i = 0; i < S; i++) { Tl[i] = 0.f; dl[i] = 0.f; }

    const float* xb = x + ((size_t)b * NTOK + (size_t)c * NC) * D;
    const int dd = tid & 63, ip = tid >> 6;

    for (int t = 0; t < NC / TILE; t++) {
        __syncthreads();  // protect xs reuse
        const float4* src = (const float4*)(xb + t * TILE * D);
#pragma unroll
        for (int idx = tid; idx < TILE * D / 4; idx += TPB_MAIN) {
            float4 v = src[idx];
            float* dst = &xs[(idx >> 4) * 65 + (idx & 15) * 4];
            dst[0] = v.x; dst[1] = v.y; dst[2] = v.z; dst[3] = v.w;
        }
        __syncthreads();

        // ---- phase 1: this thread owns token j = tid; dots + softmax + LN stats
        float dsl[S];
#pragma unroll
        for (int i = 0; i < S; i++) dsl[i] = 0.f;
        float sum = 0.f, s2 = 0.f;
        const float* xr = &xs[tid * 65];
        const float4* qh4 = (const float4*)qh;
#pragma unroll
        for (int d4 = 0; d4 < 16; d4++) {
            float x0 = xr[d4 * 4 + 0], x1 = xr[d4 * 4 + 1];
            float x2 = xr[d4 * 4 + 2], x3 = xr[d4 * 4 + 3];
            sum += (x0 + x1) + (x2 + x3);
            s2 += x0 * x0 + x1 * x1 + x2 * x2 + x3 * x3;
#pragma unroll
            for (int i = 0; i < S; i++) {
                float4 q4 = qh4[i * 16 + d4];
                dsl[i] += q4.x * x0 + q4.y * x1 + q4.z * x2 + q4.w * x3;
            }
        }
        float m = sum * (1.f / 64.f);
        float var = s2 * (1.f / 64.f) - m * m;
        float r = rsqrtf(var + 1e-5f);
        float mx = -1e30f, dots[S];
#pragma unroll
        for (int i = 0; i < S; i++) {
            dots[i] = r * (dsl[i] - m * sqs[i]) + csts[i];
            mx = fmaxf(mx, dots[i]);
        }
        float es = 0.f, ex[S];
#pragma unroll
        for (int i = 0; i < S; i++) { ex[i] = __expf(dots[i] - mx); es += ex[i]; }
        float inv = 1.f / es;
        float rm = r * m;
#pragma unroll
        for (int i = 0; i < S; i++) {
            float ai = ex[i] * inv + 1e-8f;
            dl[i] += ai;
            Tl[i] += ai * rm;
            attn_s[i * TILE + tid] = ai * r;
        }
        __syncthreads();

        // ---- phase 2: thread owns (d=dd, slots {ip,ip+2,ip+4,ip+6}); P accumulation
#pragma unroll 8
        for (int j4 = 0; j4 < TILE / 4; j4++) {
            float4 a0 = ((const float4*)(attn_s + (ip + 0) * TILE))[j4];
            float4 a1 = ((const float4*)(attn_s + (ip + 2) * TILE))[j4];
            float4 a2 = ((const float4*)(attn_s + (ip + 4) * TILE))[j4];
            float4 a3 = ((const float4*)(attn_s + (ip + 6) * TILE))[j4];
            const float* xc = &xs[j4 * 4 * 65 + dd];
            float x0 = xc[0], x1 = xc[65], x2 = xc[130], x3 = xc[195];
            acc0 += a0.x * x0 + a0.y * x1 + a0.z * x2 + a0.w * x3;
            acc1 += a1.x * x0 + a1.y * x1 + a1.z * x2 + a1.w * x3;
            acc2 += a2.x * x0 + a2.y * x1 + a2.z * x2 + a2.w * x3;
            acc3 += a3.x * x0 + a3.y * x1 + a3.z * x2 + a3.w * x3;
        }
    }

    // write P partials (each (i,d) owned by exactly one thread)
    float* Pp = &g_P[(b * CHUNKS + c) * S * D];
    Pp[(ip + 0) * D + dd] = acc0;
    Pp[(ip + 2) * D + dd] = acc1;
    Pp[(ip + 4) * D + dd] = acc2;
    Pp[(ip + 6) * D + dd] = acc3;

    // reduce T / den across 128 threads
#pragma unroll
    for (int i = 0; i < S; i++) {
#pragma unroll
        for (int off = 16; off; off >>= 1) {
            Tl[i] += __shfl_xor_sync(0xffffffffu, Tl[i], off);
            dl[i] += __shfl_xor_sync(0xffffffffu, dl[i], off);
        }
    }
    int w = tid >> 5, lane = tid & 31;
    if (lane == 0) {
#pragma unroll
        for (int i = 0; i < S; i++) { s_red[w][i] = Tl[i]; s_red[w][8 + i] = dl[i]; }
    }
    __syncthreads();
    if (tid < 16) {
        float s = s_red[0][tid] + s_red[1][tid] + s_red[2][tid] + s_red[3][tid];
        g_Td[(b * CHUNKS + c) * 16 + tid] = s;
    }
}

// ---------------- finalize: updates -> GRU -> MLP -> next q ----------------
__global__ __launch_bounds__(256) void k_fin(
    const float* __restrict__ wv, const float* __restrict__ bv,
    const float* __restrict__ w_ih, const float* __restrict__ b_ih,
    const float* __restrict__ w_hh, const float* __restrict__ b_hh,
    const float* __restrict__ w1, const float* __restrict__ b1,
    const float* __restrict__ w2, const float* __restrict__ b2,
    const float* __restrict__ g_ff, const float* __restrict__ be_ff,
    const float* __restrict__ g_sl, const float* __restrict__ be_sl,
    const float* __restrict__ g_in, const float* __restrict__ be_in,
    float* __restrict__ out, int last) {
    __shared__ float s_prev[512];
    __shared__ float s_num[512];
    __shared__ float s_upd[512];
    __shared__ float s_new[512];
    __shared__ float s_ff[512];
    __shared__ float s_h[1024];
    __shared__ float s_T[8], s_den[8];

    int b = blockIdx.x, tid = threadIdx.x;
    for (int k = tid; k < 512; k += 256) s_prev[k] = g_slots[b * 512 + k];
    if (tid < 16) {
        float s = 0.f;
        for (int c = 0; c < CHUNKS; c++) s += g_Td[(b * CHUNKS + c) * 16 + tid];
        if (tid < 8) s_T[tid] = s; else s_den[tid - 8] = s;
    }
    __syncthreads();

    // numer[i][e] = g_in[e]*(P - T_i) + den_i*beta_in[e]
    for (int k = tid; k < 512; k += 256) {
        int i = k >> 6, e = k & 63;
        float P = 0.f;
#pragma unroll
        for (int c = 0; c < CHUNKS; c++) P += g_P[(b * CHUNKS + c) * 512 + k];
        s_num[k] = g_in[e] * (P - s_T[i]) + s_den[i] * be_in[e];
    }
    __syncthreads();

    // updates = (numer @ wv)/den + bv
    for (int k = tid; k < 512; k += 256) {
        int i = k >> 6, d = k & 63;
        float s = 0.f;
#pragma unroll 8
        for (int e = 0; e < 64; e++) s += s_num[i * 64 + e] * wv[e * 64 + d];
        s_upd[k] = s / s_den[i] + bv[d];
    }
    __syncthreads();

    // GRUCell
    for (int k = tid; k < 512; k += 256) {
        int i = k >> 6, o = k & 63;
        float xr = b_ih[o], xz = b_ih[64 + o], xn = b_ih[128 + o];
        float hr = b_hh[o], hz = b_hh[64 + o], hn = b_hh[128 + o];
#pragma unroll 4
        for (int e = 0; e < 64; e++) {
            float u = s_upd[i * 64 + e], h = s_prev[i * 64 + e];
            const float* wi = &w_ih[e * 192];
            const float* wh = &w_hh[e * 192];
            xr += u * wi[o]; xz += u * wi[64 + o]; xn += u * wi[128 + o];
            hr += h * wh[o]; hz += h * wh[64 + o]; hn += h * wh[128 + o];
        }
        float r = 1.f / (1.f + __expf(-(xr + hr)));
        float z = 1.f / (1.f + __expf(-(xz + hz)));
        float n = tanhf(xn + r * hn);
        s_new[k] = (1.f - z) * n + z * s_prev[k];
    }
    __syncthreads();

    // ff = LN(slots_new, g_ff, beta_ff) — warp per slot
    {
        int w = tid >> 5, lane = tid & 31;
        float v0 = s_new[w * 64 + lane], v1 = s_new[w * 64 + 32 + lane];
        float s = v0 + v1, s2 = v0 * v0 + v1 * v1;
#pragma unroll
        for (int off = 16; off; off >>= 1) {
            s += __shfl_xor_sync(0xffffffffu, s, off);
            s2 += __shfl_xor_sync(0xffffffffu, s2, off);
        }
        float m = s * (1.f / 64.f);
        float var = s2 * (1.f / 64.f) - m * m;
        float r = rsqrtf(var + 1e-5f);
        s_ff[w * 64 + lane] = (v0 - m) * r * g_ff[lane] + be_ff[lane];
        s_ff[w * 64 + 32 + lane] = (v1 - m) * r * g_ff[lane + 32] + be_ff[lane + 32];
    }
    __syncthreads();

    // h = relu(ff @ w1 + b1)
    for (int k = tid; k < 1024; k += 256) {
        int i = k >> 7, o = k & 127;
        float s = b1[o];
#pragma unroll 8
        for (int e = 0; e < 64; e++) s += s_ff[i * 64 + e] * w1[e * 128 + o];
        s_h[k] = fmaxf(s, 0.f);
    }
    __syncthreads();

    // slots = slots_new + h @ w2 + b2
    for (int k = tid; k < 512; k += 256) {
        int i = k >> 6, d = k & 63;
        float s = b2[d];
#pragma unroll 8
        for (int e = 0; e < 128; e++) s += s_h[i * 128 + e] * w2[e * 64 + d];
        float val = s_new[k] + s;
        g_slots[b * 512 + k] = val;
        s_prev[k] = val;  // reuse buffer as new slots
        if (last) out[b * 512 + k] = val;
    }
    __syncthreads();

    if (!last) {
        compute_q_from_slots(b, s_prev, g_sl, be_sl, g_in, be_in, s_ff, s_h);
    }
}

// ---------------- launch ----------------
extern "C" void kernel_launch(void* const* d_in, const int* in_sizes, int n_in,
                              void* d_out, int out_size) {
    (void)in_sizes; (void)n_in; (void)out_size;
    const float* inputs = (const float*)d_in[0];
    const float* noise  = (const float*)d_in[1];
    const float* mu     = (const float*)d_in[2];
    const float* ls     = (const float*)d_in[3];
    const float* wq = (const float*)d_in[4];
    const float* bq = (const float*)d_in[5];
    const float* wk = (const float*)d_in[6];
    const float* bk = (const float*)d_in[7];
    const float* wv = (const float*)d_in[8];
    const float* bv = (const float*)d_in[9];
    const float* w_ih = (const float*)d_in[10];
    const float* b_ih = (const float*)d_in[11];
    const float* w_hh = (const float*)d_in[12];
    const float* b_hh = (const float*)d_in[13];
    const float* w1 = (const float*)d_in[14];
    const float* b1 = (const float*)d_in[15];
    const float* w2 = (const float*)d_in[16];
    const float* b2 = (const float*)d_in[17];
    const float* gin = (const float*)d_in[18];
    const float* bin = (const float*)d_in[19];
    const float* gsl = (const float*)d_in[20];
    const float* bsl = (const float*)d_in[21];
    const float* gff = (const float*)d_in[22];
    const float* bff = (const float*)d_in[23];
    float* out = (float*)d_out;

    k_pre<<<1, 256>>>(wq, bq, wk, bk);
    k_init<<<B, 256>>>(noise, mu, ls, gsl, bsl, gin, bin);
    for (int it = 0; it < 3; it++) {
        k_main<<<dim3(CHUNKS, B), TPB_MAIN>>>(inputs);
        k_fin<<<B, 256>>>(wv, bv, w_ih, b_ih, w_hh, b_hh, w1, b1, w2, b2,
                          gff, bff, gsl, bsl, gin, bin, out, it == 2 ? 1 : 0);
    }
}

// round 2
// speedup vs baseline: 1.4296x; 1.4296x over previous
#include <cuda_runtime.h>
#include <math.h>

#define B 64
#define NTOK 4096
#define D 64
#define S 8
#define HID 128
#define CHUNKS 8
#define NC (NTOK / CHUNKS)   /* 512 tokens per block */
#define TILE 128
#define TPB_MAIN 128

// ---------------- device scratch (no allocs allowed) ----------------
__device__ float g_slots[B * S * D];
__device__ float g_new[B * S * D];
__device__ float g_qhat[B * S * D];   // 0.125 * (q @ wk^T) * g_in
__device__ float g_sq[B * S];         // row sums of qhat
__device__ float g_cst[B * S];        // 0.125*(q~ . beta_in + q . bk)
__device__ float g_P[B * CHUNKS * S * D];  // partial P accumulators
__device__ float g_Td[B * CHUNKS * 16];    // per-chunk [T_i (8) | den_i (8)]
__device__ float g_wqk[D * D];        // wq @ wk^T
__device__ float g_bqk[D];            // bq @ wk^T
__device__ float g_wqbk[D];           // wq @ bk
__device__ float g_bqbk[1];           // bq . bk

// ---------------- precompute folded weight products ----------------
__global__ __launch_bounds__(256) void k_pre(const float* __restrict__ wq,
                                             const float* __restrict__ bq,
                                             const float* __restrict__ wk,
                                             const float* __restrict__ bk) {
    int t = threadIdx.x;
    for (int o = t; o < D * D; o += 256) {
        int e = o >> 6, e2 = o & 63;
        float s = 0.f;
        for (int d = 0; d < D; d++) s += wq[e * D + d] * wk[e2 * D + d];
        g_wqk[o] = s;
    }
    for (int e2 = t; e2 < D; e2 += 256) {
        float s = 0.f;
        for (int d = 0; d < D; d++) s += bq[d] * wk[e2 * D + d];
        g_bqk[e2] = s;
    }
    for (int e = t; e < D; e += 256) {
        float s = 0.f;
        for (int d = 0; d < D; d++) s += wq[e * D + d] * bk[d];
        g_wqbk[e] = s;
    }
    if (t == 0) {
        float s = 0.f;
        for (int d = 0; d < D; d++) s += bq[d] * bk[d];
        g_bqbk[0] = s;
    }
}

// ---------------- per-batch q-folding from current slots ----------------
// blockDim must be 256 (8 warps). s_sln: 512 floats, s_tmp: 1024 floats.
__device__ void compute_q_from_slots(int b, const float* s_slots,
                                     const float* __restrict__ g_sl,
                                     const float* __restrict__ be_sl,
                                     const float* __restrict__ g_in,
                                     const float* __restrict__ be_in,
                                     float* s_sln, float* s_tmp) {
    int tid = threadIdx.x;
    int w = tid >> 5, lane = tid & 31;
    // LayerNorm(slots) with g_sl/beta_sl: warp w handles slot w
    {
        float v0 = s_slots[w * 64 + lane];
        float v1 = s_slots[w * 64 + 32 + lane];
        float s = v0 + v1, s2 = v0 * v0 + v1 * v1;
#pragma unroll
        for (int off = 16; off; off >>= 1) {
            s += __shfl_xor_sync(0xffffffffu, s, off);
            s2 += __shfl_xor_sync(0xffffffffu, s2, off);
        }
        float m = s * (1.f / 64.f);
        float var = s2 * (1.f / 64.f) - m * m;
        float r = rsqrtf(var + 1e-5f);
        s_sln[w * 64 + lane] = (v0 - m) * r * g_sl[lane] + be_sl[lane];
        s_sln[w * 64 + 32 + lane] = (v1 - m) * r * g_sl[lane + 32] + be_sl[lane + 32];
    }
    __syncthreads();
    // q~ = sln @ wqk + bqk ; fold scale 0.125 and g_in/beta_in
    for (int rep = 0; rep < 2; rep++) {
        int idx = tid + rep * 256;
        int i = idx >> 6, e2 = idx & 63;
        float acc = g_bqk[e2];
#pragma unroll 8
        for (int e = 0; e < 64; e++) acc += s_sln[i * 64 + e] * g_wqk[e * 64 + e2];
        float qt = 0.125f * acc;
        float qh = qt * g_in[e2];
        g_qhat[b * S * D + idx] = qh;
        s_tmp[idx] = qh;
        s_tmp[512 + idx] = qt * be_in[e2];
    }
    __syncthreads();
    if (tid < S) {
        float sq = 0.f, cb = 0.f;
        for (int e2 = 0; e2 < 64; e2++) {
            sq += s_tmp[tid * 64 + e2];
            cb += s_tmp[512 + tid * 64 + e2];
        }
        float qb = g_bqbk[0];
        for (int e = 0; e < 64; e++) qb += s_sln[tid * 64 + e] * g_wqbk[e];
        g_sq[b * S + tid] = sq;
        g_cst[b * S + tid] = cb + 0.125f * qb;
    }
}

// ---------------- init: slots = mu + exp(ls)*noise, then q fold ----------------
__global__ __launch_bounds__(256) void k_init(const float* __restrict__ noise,
                                              const float* __restrict__ mu,
                                              const float* __restrict__ ls,
                                              const float* __restrict__ g_sl,
                                              const float* __restrict__ be_sl,
                                              const float* __restrict__ g_in,
                                              const float* __restrict__ be_in) {
    __shared__ float s_slots[512];
    __shared__ float s_sln[512];
    __shared__ float s_tmp[1024];
    int b = blockIdx.x, tid = threadIdx.x;
    for (int k = tid; k < 512; k += 256) {
        int d = k & 63;
        float v = mu[d] + expf(ls[d]) * noise[b * 512 + k];
        s_slots[k] = v;
        g_slots[b * 512 + k] = v;
    }
    __syncthreads();
    compute_q_from_slots(b, s_slots, g_sl, be_sl, g_in, be_in, s_sln, s_tmp);
}

// ---------------- main streaming pass (per iteration) ----------------
__global__ __launch_bounds__(TPB_MAIN) void k_main(const float* __restrict__ x) {
    __shared__ __align__(16) float xs[TILE * 65];
    __shared__ __align__(16) float attn_s[S * TILE];
    __shared__ __align__(16) float qh[S * D];
    __shared__ float sqs[S], csts[S];
    __shared__ float s_red[4][16];

    int b = blockIdx.y, c = blockIdx.x, tid = threadIdx.x;
    for (int k = tid; k < S * D; k += TPB_MAIN) qh[k] = g_qhat[b * S * D + k];
    if (tid < S) {
        sqs[tid] = g_sq[b * S + tid];
        csts[tid] = g_cst[b * S + tid];
    }

    float acc0 = 0.f, acc1 = 0.f, acc2 = 0.f, acc3 = 0.f;
    float Tl[S], dl[S];
#pragma unroll
    for (int i = 0; i < S; i++) { Tl[i] = 0.f; dl[i] = 0.f; }

    const float* xb = x + ((size_t)b * NTOK + (size_t)c * NC) * D;
    const int dd = tid & 63, ip = tid >> 6;

    for (int t = 0; t < NC / TILE; t++) {
        __syncthreads();  // protect xs reuse
        const float4* src = (const float4*)(xb + t * TILE * D);
#pragma unroll
        for (int idx = tid; idx < TILE * D / 4; idx += TPB_MAIN) {
            float4 v = src[idx];
            float* dst = &xs[(idx >> 4) * 65 + (idx & 15) * 4];
            dst[0] = v.x; dst[1] = v.y; dst[2] = v.z; dst[3] = v.w;
        }
        __syncthreads();

        // ---- phase 1: this thread owns token j = tid; dots + softmax + LN stats
        float dsl[S];
#pragma unroll
        for (int i = 0; i < S; i++) dsl[i] = 0.f;
        float sum = 0.f, s2 = 0.f;
        const float* xr = &xs[tid * 65];
        const float4* qh4 = (const float4*)qh;
#pragma unroll
        for (int d4 = 0; d4 < 16; d4++) {
            float x0 = xr[d4 * 4 + 0], x1 = xr[d4 * 4 + 1];
            float x2 = xr[d4 * 4 + 2], x3 = xr[d4 * 4 + 3];
            sum += (x0 + x1) + (x2 + x3);
            s2 += x0 * x0 + x1 * x1 + x2 * x2 + x3 * x3;
#pragma unroll
            for (int i = 0; i < S; i++) {
                float4 q4 = qh4[i * 16 + d4];
                dsl[i] += q4.x * x0 + q4.y * x1 + q4.z * x2 + q4.w * x3;
            }
        }
        float m = sum * (1.f / 64.f);
        float var = s2 * (1.f / 64.f) - m * m;
        float r = rsqrtf(var + 1e-5f);
        float mx = -1e30f, dots[S];
#pragma unroll
        for (int i = 0; i < S; i++) {
            dots[i] = r * (dsl[i] - m * sqs[i]) + csts[i];
            mx = fmaxf(mx, dots[i]);
        }
        float es = 0.f, ex[S];
#pragma unroll
        for (int i = 0; i < S; i++) { ex[i] = __expf(dots[i] - mx); es += ex[i]; }
        float inv = 1.f / es;
        float rm = r * m;
#pragma unroll
        for (int i = 0; i < S; i++) {
            float ai = ex[i] * inv + 1e-8f;
            dl[i] += ai;
            Tl[i] += ai * rm;
            attn_s[i * TILE + tid] = ai * r;
        }
        __syncthreads();

        // ---- phase 2: thread owns (d=dd, slots {ip,ip+2,ip+4,ip+6}); P accumulation
#pragma unroll 8
        for (int j4 = 0; j4 < TILE / 4; j4++) {
            float4 a0 = ((const float4*)(attn_s + (ip + 0) * TILE))[j4];
            float4 a1 = ((const float4*)(attn_s + (ip + 2) * TILE))[j4];
            float4 a2 = ((const float4*)(attn_s + (ip + 4) * TILE))[j4];
            float4 a3 = ((const float4*)(attn_s + (ip + 6) * TILE))[j4];
            const float* xc = &xs[j4 * 4 * 65 + dd];
            float x0 = xc[0], x1 = xc[65], x2 = xc[130], x3 = xc[195];
            acc0 += a0.x * x0 + a0.y * x1 + a0.z * x2 + a0.w * x3;
            acc1 += a1.x * x0 + a1.y * x1 + a1.z * x2 + a1.w * x3;
            acc2 += a2.x * x0 + a2.y * x1 + a2.z * x2 + a2.w * x3;
            acc3 += a3.x * x0 + a3.y * x1 + a3.z * x2 + a3.w * x3;
        }
    }

    // write P partials (each (i,d) owned by exactly one thread)
    float* Pp = &g_P[(b * CHUNKS + c) * S * D];
    Pp[(ip + 0) * D + dd] = acc0;
    Pp[(ip + 2) * D + dd] = acc1;
    Pp[(ip + 4) * D + dd] = acc2;
    Pp[(ip + 6) * D + dd] = acc3;

    // reduce T / den across 128 threads
#pragma unroll
    for (int i = 0; i < S; i++) {
#pragma unroll
        for (int off = 16; off; off >>= 1) {
            Tl[i] += __shfl_xor_sync(0xffffffffu, Tl[i], off);
            dl[i] += __shfl_xor_sync(0xffffffffu, dl[i], off);
        }
    }
    int w = tid >> 5, lane = tid & 31;
    if (lane == 0) {
#pragma unroll
        for (int i = 0; i < S; i++) { s_red[w][i] = Tl[i]; s_red[w][8 + i] = dl[i]; }
    }
    __syncthreads();
    if (tid < 16) {
        float s = s_red[0][tid] + s_red[1][tid] + s_red[2][tid] + s_red[3][tid];
        g_Td[(b * CHUNKS + c) * 16 + tid] = s;
    }
}

// ---------------- GRU stage: P-reduce -> numer -> updates -> GRU ----------------
// grid (2, B), 256 threads; block handles 4 slot rows of one batch.
__global__ __launch_bounds__(256) void k_gru(
    const float* __restrict__ wv, const float* __restrict__ bv,
    const float* __restrict__ w_ih, const float* __restrict__ b_ih,
    const float* __restrict__ w_hh, const float* __restrict__ b_hh,
    const float* __restrict__ g_in, const float* __restrict__ be_in) {
    __shared__ float s_num[256], s_upd[256], s_prev[256];
    __shared__ float s_T[4], s_den[4];
    int b = blockIdx.y, half = blockIdx.x, tid = threadIdx.x;
    int i_loc = tid >> 6, e = tid & 63;
    int row = half * 4 + i_loc;

    s_prev[tid] = g_slots[b * 512 + row * 64 + e];
    if (tid < 8) {
        int il = tid & 3, isden = tid >> 2;
        int idx = isden * 8 + (half * 4 + il);
        float s = 0.f;
#pragma unroll
        for (int c = 0; c < CHUNKS; c++) s += g_Td[(b * CHUNKS + c) * 16 + idx];
        if (isden) s_den[il] = s; else s_T[il] = s;
    }
    __syncthreads();

    float P = 0.f;
#pragma unroll
    for (int c = 0; c < CHUNKS; c++) P += g_P[(b * CHUNKS + c) * 512 + row * 64 + e];
    s_num[tid] = g_in[e] * (P - s_T[i_loc]) + s_den[i_loc] * be_in[e];
    __syncthreads();

    {
        float s = 0.f;
#pragma unroll 8
        for (int ee = 0; ee < 64; ee++) s += s_num[i_loc * 64 + ee] * wv[ee * 64 + e];
        s_upd[tid] = s / s_den[i_loc] + bv[e];
    }
    __syncthreads();

    {
        int o = e;
        float xr = b_ih[o], xz = b_ih[64 + o], xn = b_ih[128 + o];
        float hr = b_hh[o], hz = b_hh[64 + o], hn = b_hh[128 + o];
#pragma unroll 4
        for (int ee = 0; ee < 64; ee++) {
            float u = s_upd[i_loc * 64 + ee], h = s_prev[i_loc * 64 + ee];
            const float* wi = &w_ih[ee * 192];
            const float* wh = &w_hh[ee * 192];
            xr += u * wi[o]; xz += u * wi[64 + o]; xn += u * wi[128 + o];
            hr += h * wh[o]; hz += h * wh[64 + o]; hn += h * wh[128 + o];
        }
        float r = 1.f / (1.f + __expf(-(xr + hr)));
        float z = 1.f / (1.f + __expf(-(xz + hz)));
        float n = tanhf(xn + r * hn);
        g_new[b * 512 + row * 64 + e] = (1.f - z) * n + z * s_prev[tid];
    }
}

// ---------------- MLP stage: LN -> w1/relu -> w2 + residual ----------------
// grid (2, B), 256 threads; block handles 4 slot rows of one batch.
__global__ __launch_bounds__(256) void k_mlp(
    const float* __restrict__ w1, const float* __restrict__ b1,
    const float* __restrict__ w2, const float* __restrict__ b2,
    const float* __restrict__ g_ff, const float* __restrict__ be_ff,
    float* __restrict__ out, int last) {
    __shared__ float s_new[256], s_ff[256], s_h[512];
    __shared__ float red[8][2];
    int b = blockIdx.y, half = blockIdx.x, tid = threadIdx.x;
    int i_loc = tid >> 6, e = tid & 63;
    int row = half * 4 + i_loc;
    int wid = tid >> 5, lane = tid & 31;

    float v = g_new[b * 512 + row * 64 + e];
    s_new[tid] = v;

    // LN: each of the 8 warps holds half a row; reduce in-warp, combine via smem
    float s1 = v, s2v = v * v;
#pragma unroll
    for (int off = 16; off; off >>= 1) {
        s1 += __shfl_xor_sync(0xffffffffu, s1, off);
        s2v += __shfl_xor_sync(0xffffffffu, s2v, off);
    }
    if (lane == 0) { red[wid][0] = s1; red[wid][1] = s2v; }
    __syncthreads();
    {
        int w0 = i_loc * 2;
        float sum = red[w0][0] + red[w0 + 1][0];
        float sq = red[w0][1] + red[w0 + 1][1];
        float m = sum * (1.f / 64.f);
        float var = sq * (1.f / 64.f) - m * m;
        float r = rsqrtf(var + 1e-5f);
        s_ff[tid] = (v - m) * r * g_ff[e] + be_ff[e];
    }
    __syncthreads();

    // h = relu(ff @ w1 + b1): 512 outputs, 2 per thread
#pragma unroll
    for (int rep = 0; rep < 2; rep++) {
        int idx = tid + rep * 256;
        int i = idx >> 7, o = idx & 127;
        float s = b1[o];
#pragma unroll 8
        for (int ee = 0; ee < 64; ee++) s += s_ff[i * 64 + ee] * w1[ee * 128 + o];
        s_h[idx] = fmaxf(s, 0.f);
    }
    __syncthreads();

    // slots = new + h @ w2 + b2
    {
        float s = b2[e];
#pragma unroll 8
        for (int ee = 0; ee < 128; ee++) s += s_h[i_loc * 128 + ee] * w2[ee * 64 + e];
        float val = s_new[tid] + s;
        g_slots[b * 512 + row * 64 + e] = val;
        if (last) out[b * 512 + row * 64 + e] = val;
    }
}

// ---------------- q-fold for next iteration ----------------
__global__ __launch_bounds__(256) void k_qfold(const float* __restrict__ g_sl,
                                               const float* __restrict__ be_sl,
                                               const float* __restrict__ g_in,
                                               const float* __restrict__ be_in) {
    __shared__ float s_slots[512];
    __shared__ float s_sln[512];
    __shared__ float s_tmp[1024];
    int b = blockIdx.x, tid = threadIdx.x;
    for (int k = tid; k < 512; k += 256) s_slots[k] = g_slots[b * 512 + k];
    __syncthreads();
    compute_q_from_slots(b, s_slots, g_sl, be_sl, g_in, be_in, s_sln, s_tmp);
}

// ---------------- launch ----------------
extern "C" void kernel_launch(void* const* d_in, const int* in_sizes, int n_in,
                              void* d_out, int out_size) {
    (void)in_sizes; (void)n_in; (void)out_size;
    const float* inputs = (const float*)d_in[0];
    const float* noise  = (const float*)d_in[1];
    const float* mu     = (const float*)d_in[2];
    const float* ls     = (const float*)d_in[3];
    const float* wq = (const float*)d_in[4];
    const float* bq = (const float*)d_in[5];
    const float* wk = (const float*)d_in[6];
    const float* bk = (const float*)d_in[7];
    const float* wv = (const float*)d_in[8];
    const float* bv = (const float*)d_in[9];
    const float* w_ih = (const float*)d_in[10];
    const float* b_ih = (const float*)d_in[11];
    const float* w_hh = (const float*)d_in[12];
    const float* b_hh = (const float*)d_in[13];
    const float* w1 = (const float*)d_in[14];
    const float* b1 = (const float*)d_in[15];
    const float* w2 = (const float*)d_in[16];
    const float* b2 = (const float*)d_in[17];
    const float* gin = (const float*)d_in[18];
    const float* bin = (const float*)d_in[19];
    const float* gsl = (const float*)d_in[20];
    const float* bsl = (const float*)d_in[21];
    const float* gff = (const float*)d_in[22];
    const float* bff = (const float*)d_in[23];
    float* out = (float*)d_out;

    k_pre<<<1, 256>>>(wq, bq, wk, bk);
    k_init<<<B, 256>>>(noise, mu, ls, gsl, bsl, gin, bin);
    for (int it = 0; it < 3; it++) {
        k_main<<<dim3(CHUNKS, B), TPB_MAIN>>>(inputs);
        k_gru<<<dim3(2, B), 256>>>(wv, bv, w_ih, b_ih, w_hh, b_hh, gin, bin);
        k_mlp<<<dim3(2, B), 256>>>(w1, b1, w2, b2, gff, bff, out, it == 2 ? 1 : 0);
        if (it < 2) k_qfold<<<B, 256>>>(gsl, bsl, gin, bin);
    }
}

// round 3
// speedup vs baseline: 1.6370x; 1.1450x over previous
#include <cuda_runtime.h>
#include <math.h>

#define B 64
#define NTOK 4096
#define D 64
#define S 8
#define HID 128
#define CHUNKS 16
#define NC (NTOK / CHUNKS)   /* 256 tokens per block */
#define TILE 128
#define TPB_MAIN 128

// ---------------- device scratch (no allocs allowed) ----------------
__device__ float g_slots[B * S * D];
__device__ float g_qhat[B * S * D];   // 0.125 * (q @ wk^T) * g_in
__device__ float g_sq[B * S];         // row sums of qhat
__device__ float g_cst[B * S];        // 0.125*(q~ . beta_in + q . bk)
__device__ float g_P[B * CHUNKS * S * D];  // partial P accumulators
__device__ float g_Td[B * CHUNKS * 16];    // per-chunk [T_i (8) | den_i (8)]
__device__ float g_wqk[D * D];        // wq @ wk^T
__device__ float g_bqk[D];            // bq @ wk^T
__device__ float g_wqbk[D];           // wq @ bk
__device__ float g_bqbk[1];           // bq . bk

// ---------------- precompute folded weight products ----------------
__global__ __launch_bounds__(256) void k_pre(const float* __restrict__ wq,
                                             const float* __restrict__ bq,
                                             const float* __restrict__ wk,
                                             const float* __restrict__ bk) {
    int t = threadIdx.x;
    for (int o = t; o < D * D; o += 256) {
        int e = o >> 6, e2 = o & 63;
        float s = 0.f;
        for (int d = 0; d < D; d++) s += wq[e * D + d] * wk[e2 * D + d];
        g_wqk[o] = s;
    }
    for (int e2 = t; e2 < D; e2 += 256) {
        float s = 0.f;
        for (int d = 0; d < D; d++) s += bq[d] * wk[e2 * D + d];
        g_bqk[e2] = s;
    }
    for (int e = t; e < D; e += 256) {
        float s = 0.f;
        for (int d = 0; d < D; d++) s += wq[e * D + d] * bk[d];
        g_wqbk[e] = s;
    }
    if (t == 0) {
        float s = 0.f;
        for (int d = 0; d < D; d++) s += bq[d] * bk[d];
        g_bqbk[0] = s;
    }
}

// ---------------- per-batch q-folding (used by k_init only) ----------------
__device__ void compute_q_from_slots(int b, const float* s_slots,
                                     const float* __restrict__ g_sl,
                                     const float* __restrict__ be_sl,
                                     const float* __restrict__ g_in,
                                     const float* __restrict__ be_in,
                                     float* s_sln, float* s_tmp) {
    int tid = threadIdx.x;
    int w = tid >> 5, lane = tid & 31;
    {
        float v0 = s_slots[w * 64 + lane];
        float v1 = s_slots[w * 64 + 32 + lane];
        float s = v0 + v1, s2 = v0 * v0 + v1 * v1;
#pragma unroll
        for (int off = 16; off; off >>= 1) {
            s += __shfl_xor_sync(0xffffffffu, s, off);
            s2 += __shfl_xor_sync(0xffffffffu, s2, off);
        }
        float m = s * (1.f / 64.f);
        float var = s2 * (1.f / 64.f) - m * m;
        float r = rsqrtf(var + 1e-5f);
        s_sln[w * 64 + lane] = (v0 - m) * r * g_sl[lane] + be_sl[lane];
        s_sln[w * 64 + 32 + lane] = (v1 - m) * r * g_sl[lane + 32] + be_sl[lane + 32];
    }
    __syncthreads();
    for (int rep = 0; rep < 2; rep++) {
        int idx = tid + rep * 256;
        int i = idx >> 6, e2 = idx & 63;
        float acc = g_bqk[e2];
#pragma unroll 8
        for (int e = 0; e < 64; e++) acc += s_sln[i * 64 + e] * g_wqk[e * 64 + e2];
        float qt = 0.125f * acc;
        float qh = qt * g_in[e2];
        g_qhat[b * S * D + idx] = qh;
        s_tmp[idx] = qh;
        s_tmp[512 + idx] = qt * be_in[e2];
    }
    __syncthreads();
    if (tid < S) {
        float sq = 0.f, cb = 0.f;
        for (int e2 = 0; e2 < 64; e2++) {
            sq += s_tmp[tid * 64 + e2];
            cb += s_tmp[512 + tid * 64 + e2];
        }
        float qb = g_bqbk[0];
        for (int e = 0; e < 64; e++) qb += s_sln[tid * 64 + e] * g_wqbk[e];
        g_sq[b * S + tid] = sq;
        g_cst[b * S + tid] = cb + 0.125f * qb;
    }
}

// ---------------- init: slots = mu + exp(ls)*noise, then q fold ----------------
__global__ __launch_bounds__(256) void k_init(const float* __restrict__ noise,
                                              const float* __restrict__ mu,
                                              const float* __restrict__ ls,
                                              const float* __restrict__ g_sl,
                                              const float* __restrict__ be_sl,
                                              const float* __restrict__ g_in,
                                              const float* __restrict__ be_in) {
    __shared__ float s_slots[512];
    __shared__ float s_sln[512];
    __shared__ float s_tmp[1024];
    int b = blockIdx.x, tid = threadIdx.x;
    for (int k = tid; k < 512; k += 256) {
        int d = k & 63;
        float v = mu[d] + expf(ls[d]) * noise[b * 512 + k];
        s_slots[k] = v;
        g_slots[b * 512 + k] = v;
    }
    __syncthreads();
    compute_q_from_slots(b, s_slots, g_sl, be_sl, g_in, be_in, s_sln, s_tmp);
}

// ---------------- main streaming pass (per iteration) ----------------
__global__ __launch_bounds__(TPB_MAIN) void k_main(const float* __restrict__ x) {
    __shared__ __align__(16) float xs[TILE * 65];
    __shared__ __align__(16) float attn_s[S * TILE];
    __shared__ __align__(16) float qh[S * D];
    __shared__ float sqs[S], csts[S];
    __shared__ float s_red[4][16];

    int b = blockIdx.y, c = blockIdx.x, tid = threadIdx.x;
    for (int k = tid; k < S * D; k += TPB_MAIN) qh[k] = g_qhat[b * S * D + k];
    if (tid < S) {
        sqs[tid] = g_sq[b * S + tid];
        csts[tid] = g_cst[b * S + tid];
    }

    float acc0 = 0.f, acc1 = 0.f, acc2 = 0.f, acc3 = 0.f;
    float Tl[S], dl[S];
#pragma unroll
    for (int i = 0; i < S; i++) { Tl[i] = 0.f; dl[i] = 0.f; }

    const float* xb = x + ((size_t)b * NTOK + (size_t)c * NC) * D;
    const int dd = tid & 63, ip = tid >> 6;

    for (int t = 0; t < NC / TILE; t++) {
        __syncthreads();  // protect xs reuse
        const float4* src = (const float4*)(xb + t * TILE * D);
#pragma unroll
        for (int idx = tid; idx < TILE * D / 4; idx += TPB_MAIN) {
            float4 v = src[idx];
            float* dst = &xs[(idx >> 4) * 65 + (idx & 15) * 4];
            dst[0] = v.x; dst[1] = v.y; dst[2] = v.z; dst[3] = v.w;
        }
        __syncthreads();

        // ---- phase 1: this thread owns token j = tid
        float dsl[S];
#pragma unroll
        for (int i = 0; i < S; i++) dsl[i] = 0.f;
        float sum = 0.f, s2 = 0.f;
        const float* xr = &xs[tid * 65];
        const float4* qh4 = (const float4*)qh;
#pragma unroll
        for (int d4 = 0; d4 < 16; d4++) {
            float x0 = xr[d4 * 4 + 0], x1 = xr[d4 * 4 + 1];
            float x2 = xr[d4 * 4 + 2], x3 = xr[d4 * 4 + 3];
            sum += (x0 + x1) + (x2 + x3);
            s2 += x0 * x0 + x1 * x1 + x2 * x2 + x3 * x3;
#pragma unroll
            for (int i = 0; i < S; i++) {
                float4 q4 = qh4[i * 16 + d4];
                dsl[i] += q4.x * x0 + q4.y * x1 + q4.z * x2 + q4.w * x3;
            }
        }
        float m = sum * (1.f / 64.f);
        float var = s2 * (1.f / 64.f) - m * m;
        float r = rsqrtf(var + 1e-5f);
        float mx = -1e30f, dots[S];
#pragma unroll
        for (int i = 0; i < S; i++) {
            dots[i] = r * (dsl[i] - m * sqs[i]) + csts[i];
            mx = fmaxf(mx, dots[i]);
        }
        float es = 0.f, ex[S];
#pragma unroll
        for (int i = 0; i < S; i++) { ex[i] = __expf(dots[i] - mx); es += ex[i]; }
        float inv = 1.f / es;
        float rm = r * m;
#pragma unroll
        for (int i = 0; i < S; i++) {
            float ai = ex[i] * inv + 1e-8f;
            dl[i] += ai;
            Tl[i] += ai * rm;
            attn_s[i * TILE + tid] = ai * r;
        }
        __syncthreads();

        // ---- phase 2: thread owns (d=dd, slots {ip,ip+2,ip+4,ip+6})
#pragma unroll 8
        for (int j4 = 0; j4 < TILE / 4; j4++) {
            float4 a0 = ((const float4*)(attn_s + (ip + 0) * TILE))[j4];
            float4 a1 = ((const float4*)(attn_s + (ip + 2) * TILE))[j4];
            float4 a2 = ((const float4*)(attn_s + (ip + 4) * TILE))[j4];
            float4 a3 = ((const float4*)(attn_s + (ip + 6) * TILE))[j4];
            const float* xc = &xs[j4 * 4 * 65 + dd];
            float x0 = xc[0], x1 = xc[65], x2 = xc[130], x3 = xc[195];
            acc0 += a0.x * x0 + a0.y * x1 + a0.z * x2 + a0.w * x3;
            acc1 += a1.x * x0 + a1.y * x1 + a1.z * x2 + a1.w * x3;
            acc2 += a2.x * x0 + a2.y * x1 + a2.z * x2 + a2.w * x3;
            acc3 += a3.x * x0 + a3.y * x1 + a3.z * x2 + a3.w * x3;
        }
    }

    float* Pp = &g_P[(b * CHUNKS + c) * S * D];
    Pp[(ip + 0) * D + dd] = acc0;
    Pp[(ip + 2) * D + dd] = acc1;
    Pp[(ip + 4) * D + dd] = acc2;
    Pp[(ip + 6) * D + dd] = acc3;

#pragma unroll
    for (int i = 0; i < S; i++) {
#pragma unroll
        for (int off = 16; off; off >>= 1) {
            Tl[i] += __shfl_xor_sync(0xffffffffu, Tl[i], off);
            dl[i] += __shfl_xor_sync(0xffffffffu, dl[i], off);
        }
    }
    int w = tid >> 5, lane = tid & 31;
    if (lane == 0) {
#pragma unroll
        for (int i = 0; i < S; i++) { s_red[w][i] = Tl[i]; s_red[w][8 + i] = dl[i]; }
    }
    __syncthreads();
    if (tid < 16) {
        float s = s_red[0][tid] + s_red[1][tid] + s_red[2][tid] + s_red[3][tid];
        g_Td[(b * CHUNKS + c) * 16 + tid] = s;
    }
}

// ---------------- fused post stage: one block per (slot, batch) ----------------
// grid (S, B), 192 threads. P-reduce -> updates -> GRU -> LN -> MLP -> qfold.
__global__ __launch_bounds__(192) void k_post(
    const float* __restrict__ wv, const float* __restrict__ bv,
    const float* __restrict__ w_ih, const float* __restrict__ b_ih,
    const float* __restrict__ w_hh, const float* __restrict__ b_hh,
    const float* __restrict__ w1, const float* __restrict__ b1,
    const float* __restrict__ w2, const float* __restrict__ b2,
    const float* __restrict__ g_ff, const float* __restrict__ be_ff,
    const float* __restrict__ g_sl, const float* __restrict__ be_sl,
    const float* __restrict__ g_in, const float* __restrict__ be_in,
    float* __restrict__ out, int last) {
    __shared__ float s_num[64], s_upd[64], s_prev[64], s_new[64], s_ff[64];
    __shared__ float s_gx[192], s_gh[192], s_h1[128], s_part[128];
    __shared__ float s_Td[2];

    int i = blockIdx.x, b = blockIdx.y, tid = threadIdx.x;
    int base = b * 512 + i * 64;

    // ---- A: load prev slots, T/den, P reduce
    if (tid < 64) s_prev[tid] = g_slots[base + tid];
    if (tid >= 64 && tid < 66) {
        int idx = (tid == 64) ? i : (8 + i);
        float s = 0.f;
#pragma unroll
        for (int c = 0; c < CHUNKS; c++) s += g_Td[(b * CHUNKS + c) * 16 + idx];
        s_Td[tid - 64] = s;
    }
    float Pacc = 0.f;
    if (tid < 64) {
#pragma unroll
        for (int c = 0; c < CHUNKS; c++) Pacc += g_P[(b * CHUNKS + c) * 512 + i * 64 + tid];
    }
    __syncthreads();
    float T = s_Td[0], den = s_Td[1];
    if (tid < 64) s_num[tid] = g_in[tid] * (Pacc - T) + den * be_in[tid];
    __syncthreads();

    // ---- B: updates = (num @ wv)/den + bv   (e-dim split 2-way)
    if (tid < 128) {
        int d = tid & 63, part = tid >> 6;
        float s = 0.f;
#pragma unroll 8
        for (int ee = part * 32; ee < part * 32 + 32; ee++)
            s += s_num[ee] * wv[ee * 64 + d];
        s_part[tid] = s;
    }
    __syncthreads();
    if (tid < 64) s_upd[tid] = (s_part[tid] + s_part[tid + 64]) / den + bv[tid];
    __syncthreads();

    // ---- C: GRU gates, thread o in [0,192)
    {
        float gx = b_ih[tid], gh = b_hh[tid];
#pragma unroll 8
        for (int ee = 0; ee < 64; ee++) {
            gx += s_upd[ee] * w_ih[ee * 192 + tid];
            gh += s_prev[ee] * w_hh[ee * 192 + tid];
        }
        s_gx[tid] = gx; s_gh[tid] = gh;
    }
    __syncthreads();
    if (tid < 64) {
        float r = 1.f / (1.f + __expf(-(s_gx[tid] + s_gh[tid])));
        float z = 1.f / (1.f + __expf(-(s_gx[64 + tid] + s_gh[64 + tid])));
        float n = tanhf(s_gx[128 + tid] + r * s_gh[128 + tid]);
        s_new[tid] = (1.f - z) * n + z * s_prev[tid];
    }
    __syncthreads();

    // ---- D: ff = LN(new, g_ff, be_ff)   (warp 0)
    if (tid < 32) {
        float v0 = s_new[tid], v1 = s_new[tid + 32];
        float s = v0 + v1, s2 = v0 * v0 + v1 * v1;
#pragma unroll
        for (int off = 16; off; off >>= 1) {
            s += __shfl_xor_sync(0xffffffffu, s, off);
            s2 += __shfl_xor_sync(0xffffffffu, s2, off);
        }
        float m = s * (1.f / 64.f);
        float var = s2 * (1.f / 64.f) - m * m;
        float r = rsqrtf(var + 1e-5f);
        s_ff[tid] = (v0 - m) * r * g_ff[tid] + be_ff[tid];
        s_ff[tid + 32] = (v1 - m) * r * g_ff[tid + 32] + be_ff[tid + 32];
    }
    __syncthreads();

    // ---- E: h1 = relu(ff @ w1 + b1), o in [0,128)
    if (tid < 128) {
        float s = b1[tid];
#pragma unroll 8
        for (int ee = 0; ee < 64; ee++) s += s_ff[ee] * w1[ee * 128 + tid];
        s_h1[tid] = fmaxf(s, 0.f);
    }
    __syncthreads();

    // ---- F: slots = new + h1 @ w2 + b2   (e-dim split 2-way over 128)
    if (tid < 128) {
        int d = tid & 63, part = tid >> 6;
        float s = 0.f;
#pragma unroll 8
        for (int ee = part * 64; ee < part * 64 + 64; ee++)
            s += s_h1[ee] * w2[ee * 64 + d];
        s_part[tid] = s;
    }
    __syncthreads();
    if (tid < 64) {
        float val = s_new[tid] + b2[tid] + s_part[tid] + s_part[tid + 64];
        g_slots[base + tid] = val;
        if (last) out[base + tid] = val;
        s_new[tid] = val;  // becomes input to qfold
    }
    if (last) return;
    __syncthreads();

    // ---- G: qfold — sln = LN(val, g_sl, be_sl)  (warp 0)
    if (tid < 32) {
        float v0 = s_new[tid], v1 = s_new[tid + 32];
        float s = v0 + v1, s2 = v0 * v0 + v1 * v1;
#pragma unroll
        for (int off = 16; off; off >>= 1) {
            s += __shfl_xor_sync(0xffffffffu, s, off);
            s2 += __shfl_xor_sync(0xffffffffu, s2, off);
        }
        float m = s * (1.f / 64.f);
        float var = s2 * (1.f / 64.f) - m * m;
        float r = rsqrtf(var + 1e-5f);
        s_ff[tid] = (v0 - m) * r * g_sl[tid] + be_sl[tid];
        s_ff[tid + 32] = (v1 - m) * r * g_sl[tid + 32] + be_sl[tid + 32];
    }
    __syncthreads();

    // q~ = sln @ wqk + bqk  (e split 2-way)
    if (tid < 128) {
        int d = tid & 63, part = tid >> 6;
        float s = (part == 0) ? g_bqk[d] : 0.f;
#pragma unroll 8
        for (int ee = part * 32; ee < part * 32 + 32; ee++)
            s += s_ff[ee] * g_wqk[ee * 64 + d];
        s_part[tid] = s;
    }
    __syncthreads();
    if (tid < 64) {
        float qt = 0.125f * (s_part[tid] + s_part[tid + 64]);
        float qh = qt * g_in[tid];
        g_qhat[base + tid] = qh;
        s_gx[tid] = qh;
        s_gh[tid] = qt * be_in[tid];
    }
    __syncthreads();
    if (tid < 32) {
        float sq = s_gx[tid] + s_gx[tid + 32];
        float cb = s_gh[tid] + s_gh[tid + 32];
        float qb = s_ff[tid] * g_wqbk[tid] + s_ff[tid + 32] * g_wqbk[tid + 32];
#pragma unroll
        for (int off = 16; off; off >>= 1) {
            sq += __shfl_xor_sync(0xffffffffu, sq, off);
            cb += __shfl_xor_sync(0xffffffffu, cb, off);
            qb += __shfl_xor_sync(0xffffffffu, qb, off);
        }
        if (tid == 0) {
            g_sq[b * S + i] = sq;
            g_cst[b * S + i] = cb + 0.125f * (qb + g_bqbk[0]);
        }
    }
}

// ---------------- launch ----------------
extern "C" void kernel_launch(void* const* d_in, const int* in_sizes, int n_in,
                              void* d_out, int out_size) {
    (void)in_sizes; (void)n_in; (void)out_size;
    const float* inputs = (const float*)d_in[0];
    const float* noise  = (const float*)d_in[1];
    const float* mu     = (const float*)d_in[2];
    const float* ls     = (const float*)d_in[3];
    const float* wq = (const float*)d_in[4];
    const float* bq = (const float*)d_in[5];
    const float* wk = (const float*)d_in[6];
    const float* bk = (const float*)d_in[7];
    const float* wv = (const float*)d_in[8];
    const float* bv = (const float*)d_in[9];
    const float* w_ih = (const float*)d_in[10];
    const float* b_ih = (const float*)d_in[11];
    const float* w_hh = (const float*)d_in[12];
    const float* b_hh = (const float*)d_in[13];
    const float* w1 = (const float*)d_in[14];
    const float* b1 = (const float*)d_in[15];
    const float* w2 = (const float*)d_in[16];
    const float* b2 = (const float*)d_in[17];
    const float* gin = (const float*)d_in[18];
    const float* bin = (const float*)d_in[19];
    const float* gsl = (const float*)d_in[20];
    const float* bsl = (const float*)d_in[21];
    const float* gff = (const float*)d_in[22];
    const float* bff = (const float*)d_in[23];
    float* out = (float*)d_out;

    k_pre<<<1, 256>>>(wq, bq, wk, bk);
    k_init<<<B, 256>>>(noise, mu, ls, gsl, bsl, gin, bin);
    for (int it = 0; it < 3; it++) {
        k_main<<<dim3(CHUNKS, B), TPB_MAIN>>>(inputs);
        k_post<<<dim3(S, B), 192>>>(wv, bv, w_ih, b_ih, w_hh, b_hh, w1, b1, w2, b2,
                                    gff, bff, gsl, bsl, gin, bin, out, it == 2 ? 1 : 0);
    }
}

// round 4
// speedup vs baseline: 1.8316x; 1.1189x over previous
#include <cuda_runtime.h>
#include <math.h>

#define B 64
#define NTOK 4096
#define D 64
#define S 8
#define HID 128
#define CHUNKS 16
#define NC (NTOK / CHUNKS)   /* 256 tokens per block */
#define TILE 128
#define TPB_MAIN 128
#define XS_STRIDE 68         /* floats per token row in smem; 68*4=272B, 16B aligned */

typedef unsigned long long u64t;

__device__ __forceinline__ u64t f2_fma(u64t a, u64t b, u64t c) {
    u64t d;
    asm("fma.rn.f32x2 %0, %1, %2, %3;" : "=l"(d) : "l"(a), "l"(b), "l"(c));
    return d;
}
__device__ __forceinline__ u64t f2_add(u64t a, u64t b) {
    u64t d;
    asm("add.rn.f32x2 %0, %1, %2;" : "=l"(d) : "l"(a), "l"(b));
    return d;
}
__device__ __forceinline__ float2 f2_unpack(u64t a) {
    float2 r;
    asm("mov.b64 {%0, %1}, %2;" : "=f"(r.x), "=f"(r.y) : "l"(a));
    return r;
}

// ---------------- device scratch (no allocs allowed) ----------------
__device__ float g_slots[B * S * D];
__device__ float g_qhat[B * S * D];   // 0.125 * (q @ wk^T) * g_in
__device__ float g_sq[B * S];         // row sums of qhat
__device__ float g_cst[B * S];        // 0.125*(q~ . beta_in + q . bk)
__device__ float g_P[B * CHUNKS * S * D];  // partial P accumulators
__device__ float g_Td[B * CHUNKS * 16];    // per-chunk [T_i (8) | den_i (8)]
__device__ float g_wqk[D * D];        // wq @ wk^T
__device__ float g_bqk[D];            // bq @ wk^T
__device__ float g_wqbk[D];           // wq @ bk
__device__ float g_bqbk[1];           // bq . bk

// ---------------- precompute folded weight products ----------------
__global__ __launch_bounds__(256) void k_pre(const float* __restrict__ wq,
                                             const float* __restrict__ bq,
                                             const float* __restrict__ wk,
                                             const float* __restrict__ bk) {
    int t = threadIdx.x;
    for (int o = t; o < D * D; o += 256) {
        int e = o >> 6, e2 = o & 63;
        float s = 0.f;
        for (int d = 0; d < D; d++) s += wq[e * D + d] * wk[e2 * D + d];
        g_wqk[o] = s;
    }
    for (int e2 = t; e2 < D; e2 += 256) {
        float s = 0.f;
        for (int d = 0; d < D; d++) s += bq[d] * wk[e2 * D + d];
        g_bqk[e2] = s;
    }
    for (int e = t; e < D; e += 256) {
        float s = 0.f;
        for (int d = 0; d < D; d++) s += wq[e * D + d] * bk[d];
        g_wqbk[e] = s;
    }
    if (t == 0) {
        float s = 0.f;
        for (int d = 0; d < D; d++) s += bq[d] * bk[d];
        g_bqbk[0] = s;
    }
}

// ---------------- per-batch q-folding (used by k_init only) ----------------
__device__ void compute_q_from_slots(int b, const float* s_slots,
                                     const float* __restrict__ g_sl,
                                     const float* __restrict__ be_sl,
                                     const float* __restrict__ g_in,
                                     const float* __restrict__ be_in,
                                     float* s_sln, float* s_tmp) {
    int tid = threadIdx.x;
    int w = tid >> 5, lane = tid & 31;
    {
        float v0 = s_slots[w * 64 + lane];
        float v1 = s_slots[w * 64 + 32 + lane];
        float s = v0 + v1, s2 = v0 * v0 + v1 * v1;
#pragma unroll
        for (int off = 16; off; off >>= 1) {
            s += __shfl_xor_sync(0xffffffffu, s, off);
            s2 += __shfl_xor_sync(0xffffffffu, s2, off);
        }
        float m = s * (1.f / 64.f);
        float var = s2 * (1.f / 64.f) - m * m;
        float r = rsqrtf(var + 1e-5f);
        s_sln[w * 64 + lane] = (v0 - m) * r * g_sl[lane] + be_sl[lane];
        s_sln[w * 64 + 32 + lane] = (v1 - m) * r * g_sl[lane + 32] + be_sl[lane + 32];
    }
    __syncthreads();
    for (int rep = 0; rep < 2; rep++) {
        int idx = tid + rep * 256;
        int i = idx >> 6, e2 = idx & 63;
        float acc = g_bqk[e2];
#pragma unroll 8
        for (int e = 0; e < 64; e++) acc += s_sln[i * 64 + e] * g_wqk[e * 64 + e2];
        float qt = 0.125f * acc;
        float qh = qt * g_in[e2];
        g_qhat[b * S * D + idx] = qh;
        s_tmp[idx] = qh;
        s_tmp[512 + idx] = qt * be_in[e2];
    }
    __syncthreads();
    if (tid < S) {
        float sq = 0.f, cb = 0.f;
        for (int e2 = 0; e2 < 64; e2++) {
            sq += s_tmp[tid * 64 + e2];
            cb += s_tmp[512 + tid * 64 + e2];
        }
        float qb = g_bqbk[0];
        for (int e = 0; e < 64; e++) qb += s_sln[tid * 64 + e] * g_wqbk[e];
        g_sq[b * S + tid] = sq;
        g_cst[b * S + tid] = cb + 0.125f * qb;
    }
}

// ---------------- init ----------------
__global__ __launch_bounds__(256) void k_init(const float* __restrict__ noise,
                                              const float* __restrict__ mu,
                                              const float* __restrict__ ls,
                                              const float* __restrict__ g_sl,
                                              const float* __restrict__ be_sl,
                                              const float* __restrict__ g_in,
                                              const float* __restrict__ be_in) {
    __shared__ float s_slots[512];
    __shared__ float s_sln[512];
    __shared__ float s_tmp[1024];
    int b = blockIdx.x, tid = threadIdx.x;
    for (int k = tid; k < 512; k += 256) {
        int d = k & 63;
        float v = mu[d] + expf(ls[d]) * noise[b * 512 + k];
        s_slots[k] = v;
        g_slots[b * 512 + k] = v;
    }
    __syncthreads();
    compute_q_from_slots(b, s_slots, g_sl, be_sl, g_in, be_in, s_sln, s_tmp);
}

// ---------------- main streaming pass (per iteration) ----------------
__global__ __launch_bounds__(TPB_MAIN) void k_main(const float* __restrict__ x) {
    __shared__ __align__(16) float xs[TILE * XS_STRIDE];
    __shared__ __align__(16) float attn_s[S * TILE];
    __shared__ __align__(16) float qh[S * D];
    __shared__ float sqs[S], csts[S];
    __shared__ float s_red[4][16];

    int b = blockIdx.y, c = blockIdx.x, tid = threadIdx.x;
    for (int k = tid; k < S * D; k += TPB_MAIN) qh[k] = g_qhat[b * S * D + k];
    if (tid < S) {
        sqs[tid] = g_sq[b * S + tid];
        csts[tid] = g_cst[b * S + tid];
    }

    float acc0 = 0.f, acc1 = 0.f, acc2 = 0.f, acc3 = 0.f;
    float Tl[S], dl[S];
#pragma unroll
    for (int i = 0; i < S; i++) { Tl[i] = 0.f; dl[i] = 0.f; }

    const float* xb = x + ((size_t)b * NTOK + (size_t)c * NC) * D;
    const int dd = tid & 63, ip = tid >> 6;

    for (int t = 0; t < NC / TILE; t++) {
        __syncthreads();  // protect xs reuse
        const float4* src = (const float4*)(xb + t * TILE * D);
#pragma unroll
        for (int idx = tid; idx < TILE * D / 4; idx += TPB_MAIN) {
            float4 v = src[idx];
            float* dst = &xs[(idx >> 4) * XS_STRIDE + (idx & 15) * 4];
            dst[0] = v.x; dst[1] = v.y; dst[2] = v.z; dst[3] = v.w;
        }
        __syncthreads();

        // ---- phase 1 (packed f32x2): thread owns token j = tid
        u64t dslP[S];
#pragma unroll
        for (int i = 0; i < S; i++) dslP[i] = 0ULL;
        u64t sA = 0ULL, sB = 0ULL, qA = 0ULL, qB = 0ULL;
        const ulonglong2* xr2 = (const ulonglong2*)&xs[tid * XS_STRIDE];
        const ulonglong2* qh2 = (const ulonglong2*)qh;
#pragma unroll
        for (int d4 = 0; d4 < 16; d4++) {
            ulonglong2 xp = xr2[d4];
            sA = f2_add(sA, xp.x);
            sB = f2_add(sB, xp.y);
            qA = f2_fma(xp.x, xp.x, qA);
            qB = f2_fma(xp.y, xp.y, qB);
#pragma unroll
            for (int i = 0; i < S; i++) {
                ulonglong2 qp = qh2[i * 16 + d4];
                dslP[i] = f2_fma(qp.x, xp.x, dslP[i]);
                dslP[i] = f2_fma(qp.y, xp.y, dslP[i]);
            }
        }
        float2 sfin = f2_unpack(f2_add(sA, sB));
        float2 qfin = f2_unpack(f2_add(qA, qB));
        float sum = sfin.x + sfin.y;
        float s2 = qfin.x + qfin.y;

        float m = sum * (1.f / 64.f);
        float var = s2 * (1.f / 64.f) - m * m;
        float r = rsqrtf(var + 1e-5f);
        float mx = -1e30f, dots[S];
#pragma unroll
        for (int i = 0; i < S; i++) {
            float2 dp = f2_unpack(dslP[i]);
            float dsl = dp.x + dp.y;
            dots[i] = r * (dsl - m * sqs[i]) + csts[i];
            mx = fmaxf(mx, dots[i]);
        }
        float es = 0.f, ex[S];
#pragma unroll
        for (int i = 0; i < S; i++) { ex[i] = __expf(dots[i] - mx); es += ex[i]; }
        float inv = 1.f / es;
        float rm = r * m;
#pragma unroll
        for (int i = 0; i < S; i++) {
            float ai = ex[i] * inv + 1e-8f;
            dl[i] += ai;
            Tl[i] += ai * rm;
            attn_s[i * TILE + tid] = ai * r;
        }
        __syncthreads();

        // ---- phase 2: thread owns (d=dd, slots {ip,ip+2,ip+4,ip+6})
#pragma unroll 8
        for (int j4 = 0; j4 < TILE / 4; j4++) {
            float4 a0 = ((const float4*)(attn_s + (ip + 0) * TILE))[j4];
            float4 a1 = ((const float4*)(attn_s + (ip + 2) * TILE))[j4];
            float4 a2 = ((const float4*)(attn_s + (ip + 4) * TILE))[j4];
            float4 a3 = ((const float4*)(attn_s + (ip + 6) * TILE))[j4];
            const float* xc = &xs[j4 * 4 * XS_STRIDE + dd];
            float x0 = xc[0], x1 = xc[XS_STRIDE], x2 = xc[2 * XS_STRIDE], x3 = xc[3 * XS_STRIDE];
            acc0 += a0.x * x0 + a0.y * x1 + a0.z * x2 + a0.w * x3;
            acc1 += a1.x * x0 + a1.y * x1 + a1.z * x2 + a1.w * x3;
            acc2 += a2.x * x0 + a2.y * x1 + a2.z * x2 + a2.w * x3;
            acc3 += a3.x * x0 + a3.y * x1 + a3.z * x2 + a3.w * x3;
        }
    }

    float* Pp = &g_P[(b * CHUNKS + c) * S * D];
    Pp[(ip + 0) * D + dd] = acc0;
    Pp[(ip + 2) * D + dd] = acc1;
    Pp[(ip + 4) * D + dd] = acc2;
    Pp[(ip + 6) * D + dd] = acc3;

#pragma unroll
    for (int i = 0; i < S; i++) {
#pragma unroll
        for (int off = 16; off; off >>= 1) {
            Tl[i] += __shfl_xor_sync(0xffffffffu, Tl[i], off);
            dl[i] += __shfl_xor_sync(0xffffffffu, dl[i], off);
        }
    }
    int w = tid >> 5, lane = tid & 31;
    if (lane == 0) {
#pragma unroll
        for (int i = 0; i < S; i++) { s_red[w][i] = Tl[i]; s_red[w][8 + i] = dl[i]; }
    }
    __syncthreads();
    if (tid < 16) {
        float s = s_red[0][tid] + s_red[1][tid] + s_red[2][tid] + s_red[3][tid];
        g_Td[(b * CHUNKS + c) * 16 + tid] = s;
    }
}

// ---------------- fused post stage: grid (S, B), 384 threads ----------------
__global__ __launch_bounds__(384) void k_post(
    const float* __restrict__ wv, const float* __restrict__ bv,
    const float* __restrict__ w_ih, const float* __restrict__ b_ih,
    const float* __restrict__ w_hh, const float* __restrict__ b_hh,
    const float* __restrict__ w1, const float* __restrict__ b1,
    const float* __restrict__ w2, const float* __restrict__ b2,
    const float* __restrict__ g_ff, const float* __restrict__ be_ff,
    const float* __restrict__ g_sl, const float* __restrict__ be_sl,
    const float* __restrict__ g_in, const float* __restrict__ be_in,
    float* __restrict__ out, int last) {
    __shared__ float s_prev[64], s_num[64], s_upd[64], s_new[64], s_ff[64];
    __shared__ float s_p[256];
    __shared__ float s_gx[384], s_gh[384];
    __shared__ float s_h1[128];
    __shared__ float s_Td[2];

    int i = blockIdx.x, b = blockIdx.y, tid = threadIdx.x;
    int base = b * 512 + i * 64;

    // ---- A: prev slots, T/den, P reduce (4-way over chunks)
    if (tid < 64) {
        s_prev[tid] = g_slots[base + tid];
    } else if (tid < 66) {
        int idx = (tid == 64) ? i : (8 + i);
        float s = 0.f;
#pragma unroll
        for (int c = 0; c < CHUNKS; c++) s += g_Td[(b * CHUNKS + c) * 16 + idx];
        s_Td[tid - 64] = s;
    }
    if (tid >= 128) {
        int t2 = tid - 128, d = t2 & 63, part = t2 >> 6;
        float s = 0.f;
#pragma unroll
        for (int c = part * 4; c < part * 4 + 4; c++)
            s += g_P[(b * CHUNKS + c) * 512 + i * 64 + d];
        s_p[t2] = s;
    }
    __syncthreads();
    if (tid < 64) {
        float Pa = s_p[tid] + s_p[tid + 64] + s_p[tid + 128] + s_p[tid + 192];
        s_num[tid] = g_in[tid] * (Pa - s_Td[0]) + s_Td[1] * be_in[tid];
    }
    __syncthreads();

    // ---- B: updates = (num @ wv)/den + bv   (4-way e-split, 16-deep)
    if (tid < 256) {
        int d = tid & 63, part = tid >> 6;
        float s = 0.f;
#pragma unroll
        for (int ee = part * 16; ee < part * 16 + 16; ee++)
            s += s_num[ee] * wv[ee * 64 + d];
        s_p[tid] = s;
    }
    __syncthreads();
    if (tid < 64)
        s_upd[tid] = (s_p[tid] + s_p[tid + 64] + s_p[tid + 128] + s_p[tid + 192]) / s_Td[1] + bv[tid];
    __syncthreads();

    // ---- C: GRU gate partials (2-way e-split, 32-deep)
    {
        int half = tid >= 192 ? 1 : 0;
        int o = tid - half * 192;
        float gx = half ? 0.f : b_ih[o];
        float gh = half ? 0.f : b_hh[o];
#pragma unroll
        for (int ee = half * 32; ee < half * 32 + 32; ee++) {
            gx += s_upd[ee] * w_ih[ee * 192 + o];
            gh += s_prev[ee] * w_hh[ee * 192 + o];
        }
        s_gx[tid] = gx;
        s_gh[tid] = gh;
    }
    __syncthreads();
    if (tid < 64) {
        float rx = s_gx[tid] + s_gx[192 + tid] + s_gh[tid] + s_gh[192 + tid];
        float zx = s_gx[64 + tid] + s_gx[256 + tid] + s_gh[64 + tid] + s_gh[256 + tid];
        float nx = s_gx[128 + tid] + s_gx[320 + tid];
        float nh = s_gh[128 + tid] + s_gh[320 + tid];
        float r = 1.f / (1.f + __expf(-rx));
        float z = 1.f / (1.f + __expf(-zx));
        float n = tanhf(nx + r * nh);
        s_new[tid] = (1.f - z) * n + z * s_prev[tid];
    }
    __syncthreads();

    // ---- D: ff = LN(new, g_ff, be_ff)   (warp 0)
    if (tid < 32) {
        float v0 = s_new[tid], v1 = s_new[tid + 32];
        float s = v0 + v1, s2 = v0 * v0 + v1 * v1;
#pragma unroll
        for (int off = 16; off; off >>= 1) {
            s += __shfl_xor_sync(0xffffffffu, s, off);
            s2 += __shfl_xor_sync(0xffffffffu, s2, off);
        }
        float m = s * (1.f / 64.f);
        float var = s2 * (1.f / 64.f) - m * m;
        float r = rsqrtf(var + 1e-5f);
        s_ff[tid] = (v0 - m) * r * g_ff[tid] + be_ff[tid];
        s_ff[tid + 32] = (v1 - m) * r * g_ff[tid + 32] + be_ff[tid + 32];
    }
    __syncthreads();

    // ---- E: h1 = relu(ff @ w1 + b1)  (2-way e-split, 32-deep)
    if (tid < 256) {
        int o = tid & 127, hf = tid >> 7;
        float s = hf ? 0.f : b1[o];
#pragma unroll
        for (int ee = hf * 32; ee < hf * 32 + 32; ee++)
            s += s_ff[ee] * w1[ee * 128 + o];
        s_p[tid] = s;
    }
    __syncthreads();
    if (tid < 128) s_h1[tid] = fmaxf(s_p[tid] + s_p[tid + 128], 0.f);
    __syncthreads();

    // ---- F: slots = new + h1 @ w2 + b2  (4-way e-split over 128, 32-deep)
    if (tid < 256) {
        int d = tid & 63, part = tid >> 6;
        float s = 0.f;
#pragma unroll
        for (int ee = part * 32; ee < part * 32 + 32; ee++)
            s += s_h1[ee] * w2[ee * 64 + d];
        s_p[tid] = s;
    }
    __syncthreads();
    if (tid < 64) {
        float val = s_new[tid] + b2[tid] + s_p[tid] + s_p[tid + 64] + s_p[tid + 128] + s_p[tid + 192];
        g_slots[base + tid] = val;
        if (last) out[base + tid] = val;
        s_new[tid] = val;
    }
    if (last) return;
    __syncthreads();

    // ---- G: qfold
    if (tid < 32) {
        float v0 = s_new[tid], v1 = s_new[tid + 32];
        float s = v0 + v1, s2 = v0 * v0 + v1 * v1;
#pragma unroll
        for (int off = 16; off; off >>= 1) {
            s += __shfl_xor_sync(0xffffffffu, s, off);
            s2 += __shfl_xor_sync(0xffffffffu, s2, off);
        }
        float m = s * (1.f / 64.f);
        float var = s2 * (1.f / 64.f) - m * m;
        float r = rsqrtf(var + 1e-5f);
        s_ff[tid] = (v0 - m) * r * g_sl[tid] + be_sl[tid];
        s_ff[tid + 32] = (v1 - m) * r * g_sl[tid + 32] + be_sl[tid + 32];
    }
    __syncthreads();

    if (tid < 256) {
        int d = tid & 63, part = tid >> 6;
        float s = part ? 0.f : g_bqk[d];
#pragma unroll
        for (int ee = part * 16; ee < part * 16 + 16; ee++)
            s += s_ff[ee] * g_wqk[ee * 64 + d];
        s_p[tid] = s;
    }
    __syncthreads();
    if (tid < 64) {
        float qt = 0.125f * (s_p[tid] + s_p[tid + 64] + s_p[tid + 128] + s_p[tid + 192]);
        float qh = qt * g_in[tid];
        g_qhat[base + tid] = qh;
        s_gx[tid] = qh;
        s_gh[tid] = qt * be_in[tid];
    }
    __syncthreads();
    if (tid < 32) {
        float sq = s_gx[tid] + s_gx[tid + 32];
        float cb = s_gh[tid] + s_gh[tid + 32];
        float qb = s_ff[tid] * g_wqbk[tid] + s_ff[tid + 32] * g_wqbk[tid + 32];
#pragma unroll
        for (int off = 16; off; off >>= 1) {
            sq += __shfl_xor_sync(0xffffffffu, sq, off);
            cb += __shfl_xor_sync(0xffffffffu, cb, off);
            qb += __shfl_xor_sync(0xffffffffu, qb, off);
        }
        if (tid == 0) {
            g_sq[b * S + i] = sq;
            g_cst[b * S + i] = cb + 0.125f * (qb + g_bqbk[0]);
        }
    }
}

// ---------------- launch ----------------
extern "C" void kernel_launch(void* const* d_in, const int* in_sizes, int n_in,
                              void* d_out, int out_size) {
    (void)in_sizes; (void)n_in; (void)out_size;
    const float* inputs = (const float*)d_in[0];
    const float* noise  = (const float*)d_in[1];
    const float* mu     = (const float*)d_in[2];
    const float* ls     = (const float*)d_in[3];
    const float* wq = (const float*)d_in[4];
    const float* bq = (const float*)d_in[5];
    const float* wk = (const float*)d_in[6];
    const float* bk = (const float*)d_in[7];
    const float* wv = (const float*)d_in[8];
    const float* bv = (const float*)d_in[9];
    const float* w_ih = (const float*)d_in[10];
    const float* b_ih = (const float*)d_in[11];
    const float* w_hh = (const float*)d_in[12];
    const float* b_hh = (const float*)d_in[13];
    const float* w1 = (const float*)d_in[14];
    const float* b1 = (const float*)d_in[15];
    const float* w2 = (const float*)d_in[16];
    const float* b2 = (const float*)d_in[17];
    const float* gin = (const float*)d_in[18];
    const float* bin = (const float*)d_in[19];
    const float* gsl = (const float*)d_in[20];
    const float* bsl = (const float*)d_in[21];
    const float* gff = (const float*)d_in[22];
    const float* bff = (const float*)d_in[23];
    float* out = (float*)d_out;

    k_pre<<<1, 256>>>(wq, bq, wk, bk);
    k_init<<<B, 256>>>(noise, mu, ls, gsl, bsl, gin, bin);
    for (int it = 0; it < 3; it++) {
        k_main<<<dim3(CHUNKS, B), TPB_MAIN>>>(inputs);
        k_post<<<dim3(S, B), 384>>>(wv, bv, w_ih, b_ih, w_hh, b_hh, w1, b1, w2, b2,
                                    gff, bff, gsl, bsl, gin, bin, out, it == 2 ? 1 : 0);
    }
}